// round 11
// baseline (speedup 1.0000x reference)
#include <cuda_runtime.h>
#include <cuda_bf16.h>
#include <stdint.h>

#define BATCH 65536
#define VOCAB 1048576

// ---------------- device scratch (no allocation allowed) ----------------
__device__ uint16_t g_bufA_hi[BATCH * 1024];
__device__ uint16_t g_bufA_lo[BATCH * 1024];
__device__ uint16_t g_bufB_hi[BATCH * 1024];
__device__ uint16_t g_bufB_lo[BATCH * 1024];
__device__ uint16_t g_wt_hi[2408448];
__device__ uint16_t g_wt_lo[2408448];

// weight offsets (transposed [N,K], K padded to mult of 32):
#define OFF_BW0 0        // [512 ,  32]
#define OFF_BW1 16384    // [256 , 512]
#define OFF_BW2 147456   // [128 , 256]
#define OFF_TW0 180224   // [1024, 512]
#define OFF_TW1 704512   // [1024,1024]
#define OFF_TW2 1753088  // [512 ,1024]
#define OFF_TW3 2277376  // [256 , 512]   total 2408448

__device__ __forceinline__ void f2hilo(float x, uint16_t &hi, uint16_t &lo) {
    __nv_bfloat16 h = __float2bfloat16(x);
    float hf = __bfloat162float(h);
    __nv_bfloat16 l = __float2bfloat16(x - hf);
    hi = __bfloat16_as_ushort(h);
    lo = __bfloat16_as_ushort(l);
}
__device__ __forceinline__ float b2f(uint16_t u) {
    return __bfloat162float(__ushort_as_bfloat16(u));
}

// ---------------- PTX helpers ----------------
__device__ __forceinline__ uint32_t smem_u32(const void* p) {
    return (uint32_t)__cvta_generic_to_shared(p);
}
__device__ __forceinline__ void cp16(uint32_t s, const void* g) {
    asm volatile("cp.async.cg.shared.global [%0], [%1], 16;\n" :: "r"(s), "l"(g));
}
#define CP_COMMIT() asm volatile("cp.async.commit_group;\n" ::: "memory")
#define CP_WAIT0()  asm volatile("cp.async.wait_group 0;\n" ::: "memory")
#define CP_WAIT1()  asm volatile("cp.async.wait_group 1;\n" ::: "memory")

__device__ __forceinline__ void mma_bf16(float* c, const uint32_t* a, const uint32_t* b) {
    asm volatile(
        "mma.sync.aligned.m16n8k16.row.col.f32.bf16.bf16.f32 "
        "{%0,%1,%2,%3}, {%4,%5,%6,%7}, {%8,%9}, {%0,%1,%2,%3};\n"
        : "+f"(c[0]), "+f"(c[1]), "+f"(c[2]), "+f"(c[3])
        : "r"(a[0]), "r"(a[1]), "r"(a[2]), "r"(a[3]), "r"(b[0]), "r"(b[1]));
}
__device__ __forceinline__ void ldsm4(uint32_t* r, uint32_t addr) {
    asm volatile("ldmatrix.sync.aligned.m8n8.x4.shared.b16 {%0,%1,%2,%3}, [%4];\n"
                 : "=r"(r[0]), "=r"(r[1]), "=r"(r[2]), "=r"(r[3])
                 : "r"(addr));
}
// SW64 swizzle for 64-byte rows
__device__ __forceinline__ uint32_t swz(uint32_t off) {
    return off ^ ((off >> 3) & 0x30);
}

// ---------------- dense input conversion ----------------
__global__ void conv_dense_kernel(const float* __restrict__ d,
                                  uint16_t* __restrict__ hi, uint16_t* __restrict__ lo) {
    int idx = blockIdx.x * blockDim.x + threadIdx.x;   // BATCH*32
    int b = idx >> 5, k = idx & 31;
    float v = (k < 13) ? d[b * 13 + k] : 0.f;
    uint16_t h, l;
    f2hilo(v, h, l);
    hi[idx] = h; lo[idx] = l;
}

// ---------------- weight transpose + hi/lo split (coalesced via smem tile) ----
__global__ void conv_wt_t_kernel(const float* __restrict__ W,
                                 uint16_t* __restrict__ hi, uint16_t* __restrict__ lo,
                                 int K, int N, int Kpad) {
    __shared__ float tile[32][65];
    const int tx = threadIdx.x & 31;
    const int ty = threadIdx.x >> 5;
    const int n0 = blockIdx.x * 32;
    const int k0 = blockIdx.y * 64;

#pragma unroll
    for (int kk = ty; kk < 64; kk += 8) {
        int k = k0 + kk, n = n0 + tx;
        tile[tx][kk] = (k < K) ? W[(size_t)k * N + n] : 0.f;
    }
    __syncthreads();

#pragma unroll
    for (int r = ty; r < 32; r += 8) {
        int n = n0 + r;
        int k = k0 + tx * 2;
        if (k < Kpad) {
            float v0 = tile[r][tx * 2], v1 = tile[r][tx * 2 + 1];
            uint16_t h0, l0, h1, l1;
            f2hilo(v0, h0, l0);
            f2hilo(v1, h1, l1);
            *(uint32_t*)&hi[(size_t)n * Kpad + k] = (uint32_t)h0 | ((uint32_t)h1 << 16);
            *(uint32_t*)&lo[(size_t)n * Kpad + k] = (uint32_t)l0 | ((uint32_t)l1 << 16);
        }
    }
}

// ---------------- bf16x3 GEMM: 256x128 block tile, warp tile 64x64 -----------
// Stage layout: Ah 16K | Al 16K | Bh 8K | Bl 8K  = 48KB, 3 stages = 144KB.
#define STAGE_B 49152
#define SOFF_AL 16384
#define SOFF_BH 32768
#define SOFF_BL 40960

__global__ __launch_bounds__(256, 1)
void gemm_hmma(const uint16_t* __restrict__ Ahi, const uint16_t* __restrict__ Alo,
               const uint16_t* __restrict__ Whi, const uint16_t* __restrict__ Wlo,
               const float* __restrict__ bias,
               uint16_t* __restrict__ Ohi, uint16_t* __restrict__ Olo,
               int Nsz, int K, int relu) {
    extern __shared__ __align__(16) uint8_t dsm[];
    const uint32_t sbase = smem_u32(dsm);

    const int tid  = threadIdx.x;
    const int lane = tid & 31;
    const int warp = tid >> 5;
    const int wm = warp >> 1;          // 0..3, m-offset 64 each
    const int wn = warp & 1;           // 0..1, n-offset 64 each
    const size_t mBase = (size_t)blockIdx.y * 256;
    const int    nBase = blockIdx.x * 128;
    const int    nch   = K >> 5;

    // cp.async: thread covers row r0 = tid>>2 (+64 steps), 16B chunk ch = tid&3.
    const int r0 = tid >> 2, ch = tid & 3;
    const uint16_t* gA0 = Ahi + (mBase + r0) * (size_t)K + ch * 8;
    const uint16_t* gA1 = Alo + (mBase + r0) * (size_t)K + ch * 8;
    const uint16_t* gB0 = Whi + (size_t)(nBase + r0) * K + ch * 8;
    const uint16_t* gB1 = Wlo + (size_t)(nBase + r0) * K + ch * 8;
    const uint32_t soff = swz((uint32_t)r0 * 64 + ch * 16);
    const size_t rowD = (size_t)64 * K;

    auto issue = [&](int c) {
        const uint32_t st = sbase + (c % 3) * STAGE_B + soff;
        const int k0 = c << 5;
#pragma unroll
        for (int rep = 0; rep < 4; rep++) {           // A: 256 rows
            cp16(st + rep * 4096,             gA0 + rep * rowD + k0);
            cp16(st + SOFF_AL + rep * 4096,   gA1 + rep * rowD + k0);
        }
#pragma unroll
        for (int rep = 0; rep < 2; rep++) {           // B: 128 rows
            cp16(st + SOFF_BH + rep * 4096,   gB0 + rep * rowD + k0);
            cp16(st + SOFF_BL + rep * 4096,   gB1 + rep * rowD + k0);
        }
    };

    float acc[4][8][4];
#pragma unroll
    for (int a = 0; a < 4; a++)
#pragma unroll
        for (int b = 0; b < 8; b++)
#pragma unroll
            for (int c = 0; c < 4; c++) acc[a][b][c] = 0.f;

    const uint32_t aRow = (uint32_t)(wm * 64 + (lane & 15)) * 64 + (lane >> 4) * 16;
    const uint32_t bRow = (uint32_t)(wn * 64 + (lane & 7) + ((lane >> 4) << 3)) * 64
                        + (((lane >> 3) & 1) << 4);

    issue(0); CP_COMMIT();
    if (nch > 1) { issue(1); CP_COMMIT(); }

    for (int c = 0; c < nch; c++) {
        if (c + 1 < nch) CP_WAIT1(); else CP_WAIT0();
        __syncthreads();
        if (c + 2 < nch) { issue(c + 2); CP_COMMIT(); }

        const uint32_t st = sbase + (c % 3) * STAGE_B;
#pragma unroll
        for (int kk = 0; kk < 2; kk++) {
            uint32_t aH[4][4], aL[4][4], bB[4][4];
#pragma unroll
            for (int mt = 0; mt < 4; mt++) {
                uint32_t off = swz(aRow + mt * 16 * 64 + kk * 32);
                ldsm4(aH[mt], st + off);
                ldsm4(aL[mt], st + SOFF_AL + off);
            }
#pragma unroll
            for (int np = 0; np < 4; np++)
                ldsm4(bB[np], st + SOFF_BH + swz(bRow + np * 16 * 64 + kk * 32));

            // pass 1: aH x bH -- 32 independent MMAs
#pragma unroll
            for (int np = 0; np < 4; np++)
#pragma unroll
                for (int mt = 0; mt < 4; mt++) {
                    mma_bf16(acc[mt][np * 2],     aH[mt], &bB[np][0]);
                    mma_bf16(acc[mt][np * 2 + 1], aH[mt], &bB[np][2]);
                }
            // pass 2: aL x bH; reload bB[np] with bL after its last use
#pragma unroll
            for (int np = 0; np < 4; np++) {
#pragma unroll
                for (int mt = 0; mt < 4; mt++) {
                    mma_bf16(acc[mt][np * 2],     aL[mt], &bB[np][0]);
                    mma_bf16(acc[mt][np * 2 + 1], aL[mt], &bB[np][2]);
                }
                ldsm4(bB[np], st + SOFF_BL + swz(bRow + np * 16 * 64 + kk * 32));
            }
            // pass 3: aH x bL -- fragments resident
#pragma unroll
            for (int np = 0; np < 4; np++)
#pragma unroll
                for (int mt = 0; mt < 4; mt++) {
                    mma_bf16(acc[mt][np * 2],     aH[mt], &bB[np][0]);
                    mma_bf16(acc[mt][np * 2 + 1], aH[mt], &bB[np][2]);
                }
        }
    }

    // epilogue: bias + relu + hi/lo split + store
#pragma unroll
    for (int mt = 0; mt < 4; mt++) {
        size_t m0 = mBase + wm * 64 + mt * 16 + (lane >> 2);
#pragma unroll
        for (int nt = 0; nt < 8; nt++) {
            int n = nBase + wn * 64 + nt * 8 + (lane & 3) * 2;
            float b0 = bias[n], b1 = bias[n + 1];
            float v0 = acc[mt][nt][0] + b0;
            float v1 = acc[mt][nt][1] + b1;
            float v2 = acc[mt][nt][2] + b0;
            float v3 = acc[mt][nt][3] + b1;
            if (relu) {
                v0 = fmaxf(v0, 0.f); v1 = fmaxf(v1, 0.f);
                v2 = fmaxf(v2, 0.f); v3 = fmaxf(v3, 0.f);
            }
            uint16_t h0, l0, h1, l1;
            f2hilo(v0, h0, l0); f2hilo(v1, h1, l1);
            *(uint32_t*)&Ohi[m0 * Nsz + n] = (uint32_t)h0 | ((uint32_t)h1 << 16);
            *(uint32_t*)&Olo[m0 * Nsz + n] = (uint32_t)l0 | ((uint32_t)l1 << 16);
            f2hilo(v2, h0, l0); f2hilo(v3, h1, l1);
            *(uint32_t*)&Ohi[(m0 + 8) * Nsz + n] = (uint32_t)h0 | ((uint32_t)h1 << 16);
            *(uint32_t*)&Olo[(m0 + 8) * Nsz + n] = (uint32_t)l0 | ((uint32_t)l1 << 16);
        }
    }
}

// ---------------- embedding gather + pairwise interaction ----------------
__global__ __launch_bounds__(256, 1)
void interact_kernel(const uint16_t* __restrict__ Hhi, const uint16_t* __restrict__ Hlo,
                     const float* __restrict__ emb, const int* __restrict__ sidx,
                     uint16_t* __restrict__ Ohi, uint16_t* __restrict__ Olo) {
    extern __shared__ float comb[];                 // 8 * 128 * 28 floats
    const int warp = threadIdx.x >> 5;
    const int lane = threadIdx.x & 31;
    const size_t s = (size_t)blockIdx.x * 8 + warp;
    float* C = comb + warp * (128 * 28);

    int idx26[26];
#pragma unroll
    for (int v = 0; v < 26; v++) idx26[v] = sidx[s * 26 + v] & (VOCAB - 1);

    {
        uint2 hh = *(const uint2*)&Hhi[s * 128 + lane * 4];
        uint2 ll = *(const uint2*)&Hlo[s * 128 + lane * 4];
        uint16_t hu[4] = {(uint16_t)(hh.x & 0xFFFF), (uint16_t)(hh.x >> 16),
                          (uint16_t)(hh.y & 0xFFFF), (uint16_t)(hh.y >> 16)};
        uint16_t lu[4] = {(uint16_t)(ll.x & 0xFFFF), (uint16_t)(ll.x >> 16),
                          (uint16_t)(ll.y & 0xFFFF), (uint16_t)(ll.y >> 16)};
#pragma unroll
        for (int j = 0; j < 4; j++) {
            float v = b2f(hu[j]) + b2f(lu[j]);
            C[(4 * lane + j) * 28 + 0] = v;
            C[(4 * lane + j) * 28 + 27] = 0.f;
        }
        *(uint2*)&Ohi[s * 512 + lane * 4] = hh;
        *(uint2*)&Olo[s * 512 + lane * 4] = ll;
    }

#pragma unroll
    for (int w0 = 0; w0 < 26; w0 += 8) {
        float4 e[8];
        const int cnt = (26 - w0 < 8) ? (26 - w0) : 8;
#pragma unroll
        for (int j = 0; j < 8; j++)
            if (j < cnt)
                e[j] = *(const float4*)&emb[(size_t)idx26[w0 + j] * 128 + lane * 4];
#pragma unroll
        for (int j = 0; j < 8; j++)
            if (j < cnt) {
                const int v = w0 + j;
                C[(4 * lane + 0) * 28 + (v + 1)] = e[j].x;
                C[(4 * lane + 1) * 28 + (v + 1)] = e[j].y;
                C[(4 * lane + 2) * 28 + (v + 1)] = e[j].z;
                C[(4 * lane + 3) * 28 + (v + 1)] = e[j].w;
            }
    }
    __syncwarp();

    if (lane < 28) {
        int rem = lane, ti = 0;
        while (rem >= 7 - ti) { rem -= 7 - ti; ti++; }
        int tj = ti + rem;

        float a4[16];
#pragma unroll
        for (int i = 0; i < 16; i++) a4[i] = 0.f;

        const float* Ca = C + 4 * ti;
        const float* Cb = C + 4 * tj;
#pragma unroll 4
        for (int k = 0; k < 128; k++) {
            float4 av = *(const float4*)(Ca + k * 28);
            float4 bv = *(const float4*)(Cb + k * 28);
            float aa[4] = {av.x, av.y, av.z, av.w};
            float bb[4] = {bv.x, bv.y, bv.z, bv.w};
#pragma unroll
            for (int i = 0; i < 4; i++)
#pragma unroll
                for (int j = 0; j < 4; j++) a4[i * 4 + j] += aa[i] * bb[j];
        }
#pragma unroll
        for (int ai = 0; ai < 4; ai++)
#pragma unroll
            for (int bi = 0; bi < 4; bi++) {
                int i = 4 * ti + ai, j = 4 * tj + bi;
                if (i <= j && j < 27) {
                    int flat = 27 * i - (i * (i - 1)) / 2 + (j - i);
                    uint16_t h, l;
                    f2hilo(a4[ai * 4 + bi], h, l);
                    Ohi[s * 512 + 128 + flat] = h;
                    Olo[s * 512 + 128 + flat] = l;
                }
            }
    } else if (lane == 28) {
        for (int c = 506; c < 512; c++) { Ohi[s * 512 + c] = 0; Olo[s * 512 + c] = 0; }
    }
}

// ---------------- final 256 -> 1 dot ----------------
__global__ void final_dot_kernel(const uint16_t* __restrict__ Ahi, const uint16_t* __restrict__ Alo,
                                 const float* __restrict__ w, const float* __restrict__ b,
                                 float* __restrict__ out) {
    const int warp = threadIdx.x >> 5;
    const int lane = threadIdx.x & 31;
    const size_t s = (size_t)blockIdx.x * 8 + warp;
    uint4 h4 = *(const uint4*)&Ahi[s * 256 + lane * 8];
    uint4 l4 = *(const uint4*)&Alo[s * 256 + lane * 8];
    uint32_t hw[4] = {h4.x, h4.y, h4.z, h4.w};
    uint32_t lw[4] = {l4.x, l4.y, l4.z, l4.w};
    float acc = 0.f;
#pragma unroll
    for (int q = 0; q < 4; q++) {
        float v0 = b2f((uint16_t)(hw[q] & 0xFFFF)) + b2f((uint16_t)(lw[q] & 0xFFFF));
        float v1 = b2f((uint16_t)(hw[q] >> 16))    + b2f((uint16_t)(lw[q] >> 16));
        acc += v0 * w[lane * 8 + q * 2];
        acc += v1 * w[lane * 8 + q * 2 + 1];
    }
#pragma unroll
    for (int o = 16; o; o >>= 1) acc += __shfl_xor_sync(0xFFFFFFFFu, acc, o);
    if (lane == 0) out[s] = acc + b[0];
}

// ---------------- host launch ----------------
extern "C" void kernel_launch(void* const* d_in, const int* in_sizes, int n_in,
                              void* d_out, int out_size) {
    const float* dense = (const float*)d_in[0];
    const int*   sidx  = (const int*)d_in[1];
    const float* emb   = (const float*)d_in[2];
    const float* bw0 = (const float*)d_in[3];  const float* bb0 = (const float*)d_in[4];
    const float* bw1 = (const float*)d_in[5];  const float* bb1 = (const float*)d_in[6];
    const float* bw2 = (const float*)d_in[7];  const float* bb2 = (const float*)d_in[8];
    const float* tw0 = (const float*)d_in[9];  const float* tb0 = (const float*)d_in[10];
    const float* tw1 = (const float*)d_in[11]; const float* tb1 = (const float*)d_in[12];
    const float* tw2 = (const float*)d_in[13]; const float* tb2 = (const float*)d_in[14];
    const float* tw3 = (const float*)d_in[15]; const float* tb3 = (const float*)d_in[16];
    const float* tw4 = (const float*)d_in[17]; const float* tb4 = (const float*)d_in[18];

    uint16_t *bufAh, *bufAl, *bufBh, *bufBl, *wth, *wtl;
    cudaGetSymbolAddress((void**)&bufAh, g_bufA_hi);
    cudaGetSymbolAddress((void**)&bufAl, g_bufA_lo);
    cudaGetSymbolAddress((void**)&bufBh, g_bufB_hi);
    cudaGetSymbolAddress((void**)&bufBl, g_bufB_lo);
    cudaGetSymbolAddress((void**)&wth, g_wt_hi);
    cudaGetSymbolAddress((void**)&wtl, g_wt_lo);

    const int DSM = 3 * STAGE_B;   // 147456
    cudaFuncSetAttribute(gemm_hmma, cudaFuncAttributeMaxDynamicSharedMemorySize, DSM);
    cudaFuncSetAttribute(interact_kernel, cudaFuncAttributeMaxDynamicSharedMemorySize, 114688);

    dim3 blk(256);

    // conversions
    conv_dense_kernel<<<BATCH * 32 / 256, blk>>>(dense, bufAh, bufAl);
    conv_wt_t_kernel<<<dim3(512 / 32, 1),   blk>>>(bw0, wth + OFF_BW0, wtl + OFF_BW0, 13,   512,  32);
    conv_wt_t_kernel<<<dim3(256 / 32, 8),   blk>>>(bw1, wth + OFF_BW1, wtl + OFF_BW1, 512,  256,  512);
    conv_wt_t_kernel<<<dim3(128 / 32, 4),   blk>>>(bw2, wth + OFF_BW2, wtl + OFF_BW2, 256,  128,  256);
    conv_wt_t_kernel<<<dim3(1024 / 32, 8),  blk>>>(tw0, wth + OFF_TW0, wtl + OFF_TW0, 506,  1024, 512);
    conv_wt_t_kernel<<<dim3(1024 / 32, 16), blk>>>(tw1, wth + OFF_TW1, wtl + OFF_TW1, 1024, 1024, 1024);
    conv_wt_t_kernel<<<dim3(512 / 32, 16),  blk>>>(tw2, wth + OFF_TW2, wtl + OFF_TW2, 1024, 512,  1024);
    conv_wt_t_kernel<<<dim3(256 / 32, 8),   blk>>>(tw3, wth + OFF_TW3, wtl + OFF_TW3, 512,  256,  512);

    // bottom MLP (grid.y = BATCH/256)
    gemm_hmma<<<dim3(4, 256), blk, DSM>>>(bufAh, bufAl, wth + OFF_BW0, wtl + OFF_BW0, bb0, bufBh, bufBl, 512, 32, 1);
    gemm_hmma<<<dim3(2, 256), blk, DSM>>>(bufBh, bufBl, wth + OFF_BW1, wtl + OFF_BW1, bb1, bufAh, bufAl, 256, 512, 1);
    gemm_hmma<<<dim3(1, 256), blk, DSM>>>(bufAh, bufAl, wth + OFF_BW2, wtl + OFF_BW2, bb2, bufBh, bufBl, 128, 256, 1);

    // gather + interaction -> [B, 512]
    interact_kernel<<<BATCH / 8, blk, 114688>>>(bufBh, bufBl, emb, sidx, bufAh, bufAl);

    // top MLP
    gemm_hmma<<<dim3(8, 256), blk, DSM>>>(bufAh, bufAl, wth + OFF_TW0, wtl + OFF_TW0, tb0, bufBh, bufBl, 1024, 512, 1);
    gemm_hmma<<<dim3(8, 256), blk, DSM>>>(bufBh, bufBl, wth + OFF_TW1, wtl + OFF_TW1, tb1, bufAh, bufAl, 1024, 1024, 1);
    gemm_hmma<<<dim3(4, 256), blk, DSM>>>(bufAh, bufAl, wth + OFF_TW2, wtl + OFF_TW2, tb2, bufBh, bufBl, 512, 1024, 1);
    gemm_hmma<<<dim3(2, 256), blk, DSM>>>(bufBh, bufBl, wth + OFF_TW3, wtl + OFF_TW3, tb3, bufAh, bufAl, 256, 512, 1);

    // final 256 -> 1
    final_dot_kernel<<<BATCH / 8, blk>>>(bufAh, bufAl, tw4, tb4, (float*)d_out);
}

// round 12
// speedup vs baseline: 1.1462x; 1.1462x over previous
#include <cuda_runtime.h>
#include <cuda_bf16.h>
#include <stdint.h>

#define BATCH 65536
#define VOCAB 1048576

// ---------------- device scratch (no allocation allowed) ----------------
__device__ uint16_t g_bufA_hi[BATCH * 1024];
__device__ uint16_t g_bufA_lo[BATCH * 1024];
__device__ uint16_t g_bufB_hi[BATCH * 1024];
__device__ uint16_t g_bufB_lo[BATCH * 1024];
__device__ uint16_t g_wt_hi[2408448];
__device__ uint16_t g_wt_lo[2408448];

// weight offsets (transposed [N,K], K padded to mult of 32):
#define OFF_BW0 0        // [512 ,  32]
#define OFF_BW1 16384    // [256 , 512]
#define OFF_BW2 147456   // [128 , 256]
#define OFF_TW0 180224   // [1024, 512]
#define OFF_TW1 704512   // [1024,1024]
#define OFF_TW2 1753088  // [512 ,1024]
#define OFF_TW3 2277376  // [256 , 512]   total 2408448

__device__ __forceinline__ void f2hilo(float x, uint16_t &hi, uint16_t &lo) {
    __nv_bfloat16 h = __float2bfloat16(x);
    float hf = __bfloat162float(h);
    __nv_bfloat16 l = __float2bfloat16(x - hf);
    hi = __bfloat16_as_ushort(h);
    lo = __bfloat16_as_ushort(l);
}
__device__ __forceinline__ float b2f(uint16_t u) {
    return __bfloat162float(__ushort_as_bfloat16(u));
}

// ---------------- PTX helpers ----------------
__device__ __forceinline__ uint32_t smem_u32(const void* p) {
    return (uint32_t)__cvta_generic_to_shared(p);
}
__device__ __forceinline__ void cp16(uint32_t s, const void* g) {
    asm volatile("cp.async.cg.shared.global [%0], [%1], 16;\n" :: "r"(s), "l"(g));
}
#define CP_COMMIT() asm volatile("cp.async.commit_group;\n" ::: "memory")
#define CP_WAIT0()  asm volatile("cp.async.wait_group 0;\n" ::: "memory")
#define CP_WAIT1()  asm volatile("cp.async.wait_group 1;\n" ::: "memory")

__device__ __forceinline__ void mma_bf16(float* c, const uint32_t* a, const uint32_t* b) {
    asm volatile(
        "mma.sync.aligned.m16n8k16.row.col.f32.bf16.bf16.f32 "
        "{%0,%1,%2,%3}, {%4,%5,%6,%7}, {%8,%9}, {%0,%1,%2,%3};\n"
        : "+f"(c[0]), "+f"(c[1]), "+f"(c[2]), "+f"(c[3])
        : "r"(a[0]), "r"(a[1]), "r"(a[2]), "r"(a[3]), "r"(b[0]), "r"(b[1]));
}
__device__ __forceinline__ void ldsm4(uint32_t* r, uint32_t addr) {
    asm volatile("ldmatrix.sync.aligned.m8n8.x4.shared.b16 {%0,%1,%2,%3}, [%4];\n"
                 : "=r"(r[0]), "=r"(r[1]), "=r"(r[2]), "=r"(r[3])
                 : "r"(addr));
}
// SW64 swizzle for 64-byte rows (GEMM tiles)
__device__ __forceinline__ uint32_t swz(uint32_t off) {
    return off ^ ((off >> 3) & 0x30);
}

// ---------------- dense input conversion ----------------
__global__ void conv_dense_kernel(const float* __restrict__ d,
                                  uint16_t* __restrict__ hi, uint16_t* __restrict__ lo) {
    int idx = blockIdx.x * blockDim.x + threadIdx.x;   // BATCH*32
    int b = idx >> 5, k = idx & 31;
    float v = (k < 13) ? d[b * 13 + k] : 0.f;
    uint16_t h, l;
    f2hilo(v, h, l);
    hi[idx] = h; lo[idx] = l;
}

// ---------------- weight transpose + hi/lo split (coalesced via smem tile) ----
__global__ void conv_wt_t_kernel(const float* __restrict__ W,
                                 uint16_t* __restrict__ hi, uint16_t* __restrict__ lo,
                                 int K, int N, int Kpad) {
    __shared__ float tile[32][65];
    const int tx = threadIdx.x & 31;
    const int ty = threadIdx.x >> 5;
    const int n0 = blockIdx.x * 32;
    const int k0 = blockIdx.y * 64;

#pragma unroll
    for (int kk = ty; kk < 64; kk += 8) {
        int k = k0 + kk, n = n0 + tx;
        tile[tx][kk] = (k < K) ? W[(size_t)k * N + n] : 0.f;
    }
    __syncthreads();

#pragma unroll
    for (int r = ty; r < 32; r += 8) {
        int n = n0 + r;
        int k = k0 + tx * 2;
        if (k < Kpad) {
            float v0 = tile[r][tx * 2], v1 = tile[r][tx * 2 + 1];
            uint16_t h0, l0, h1, l1;
            f2hilo(v0, h0, l0);
            f2hilo(v1, h1, l1);
            *(uint32_t*)&hi[(size_t)n * Kpad + k] = (uint32_t)h0 | ((uint32_t)h1 << 16);
            *(uint32_t*)&lo[(size_t)n * Kpad + k] = (uint32_t)l0 | ((uint32_t)l1 << 16);
        }
    }
}

// ---------------- bf16x3 GEMM (R10 config: 128x128, 2 CTA/SM, 3-stage) -------
#define STAGE_B 32768          // Ah 8K | Al 8K | Bh 8K | Bl 8K
#define SOFF_AL 8192
#define SOFF_BH 16384
#define SOFF_BL 24576

__global__ __launch_bounds__(256, 2)
void gemm_hmma(const uint16_t* __restrict__ Ahi, const uint16_t* __restrict__ Alo,
               const uint16_t* __restrict__ Whi, const uint16_t* __restrict__ Wlo,
               const float* __restrict__ bias,
               uint16_t* __restrict__ Ohi, uint16_t* __restrict__ Olo,
               int Nsz, int K, int relu) {
    extern __shared__ __align__(16) uint8_t dsm[];
    const uint32_t sbase = smem_u32(dsm);

    const int tid  = threadIdx.x;
    const int lane = tid & 31;
    const int warp = tid >> 5;
    const int wm = warp & 3;
    const int wn = warp >> 2;
    const size_t mBase = (size_t)blockIdx.y * 128;
    const int    nBase = blockIdx.x * 128;
    const int    nch   = K >> 5;

    const int r0 = tid >> 2, ch = tid & 3;
    const uint16_t* gp[4];
    gp[0] = Ahi + (mBase + r0) * (size_t)K + ch * 8;
    gp[1] = Alo + (mBase + r0) * (size_t)K + ch * 8;
    gp[2] = Whi + (size_t)(nBase + r0) * K + ch * 8;
    gp[3] = Wlo + (size_t)(nBase + r0) * K + ch * 8;
    const uint32_t soff = swz((uint32_t)r0 * 64 + ch * 16);
    const size_t rowD = (size_t)64 * K;

    auto issue = [&](int c) {
        const uint32_t st = sbase + (c % 3) * STAGE_B + soff;
        const int k0 = c << 5;
#pragma unroll
        for (int rg = 0; rg < 4; rg++) {
            cp16(st + rg * 8192,        gp[rg] + k0);
            cp16(st + rg * 8192 + 4096, gp[rg] + rowD + k0);
        }
    };

    float acc[2][8][4];
#pragma unroll
    for (int a = 0; a < 2; a++)
#pragma unroll
        for (int b = 0; b < 8; b++)
#pragma unroll
            for (int c = 0; c < 4; c++) acc[a][b][c] = 0.f;

    const uint32_t aRow = (uint32_t)(wm * 32 + (lane & 15)) * 64 + (lane >> 4) * 16;
    const uint32_t bRow = (uint32_t)(wn * 64 + (lane & 7) + ((lane >> 4) << 3)) * 64
                        + (((lane >> 3) & 1) << 4);

    issue(0); CP_COMMIT();
    if (nch > 1) { issue(1); CP_COMMIT(); }

    for (int c = 0; c < nch; c++) {
        if (c + 1 < nch) CP_WAIT1(); else CP_WAIT0();
        __syncthreads();
        if (c + 2 < nch) { issue(c + 2); CP_COMMIT(); }

        const uint32_t st = sbase + (c % 3) * STAGE_B;
#pragma unroll
        for (int kk = 0; kk < 2; kk++) {
            uint32_t aH[2][4], aL[2][4], bB[4][4];
#pragma unroll
            for (int mt = 0; mt < 2; mt++) {
                uint32_t off = swz(aRow + mt * 16 * 64 + kk * 32);
                ldsm4(aH[mt], st + off);
                ldsm4(aL[mt], st + SOFF_AL + off);
            }
#pragma unroll
            for (int np = 0; np < 4; np++)
                ldsm4(bB[np], st + SOFF_BH + swz(bRow + np * 16 * 64 + kk * 32));

#pragma unroll
            for (int np = 0; np < 4; np++)
#pragma unroll
                for (int mt = 0; mt < 2; mt++) {
                    mma_bf16(acc[mt][np * 2],     aH[mt], &bB[np][0]);
                    mma_bf16(acc[mt][np * 2 + 1], aH[mt], &bB[np][2]);
                }
#pragma unroll
            for (int np = 0; np < 4; np++) {
#pragma unroll
                for (int mt = 0; mt < 2; mt++) {
                    mma_bf16(acc[mt][np * 2],     aL[mt], &bB[np][0]);
                    mma_bf16(acc[mt][np * 2 + 1], aL[mt], &bB[np][2]);
                }
                ldsm4(bB[np], st + SOFF_BL + swz(bRow + np * 16 * 64 + kk * 32));
            }
#pragma unroll
            for (int np = 0; np < 4; np++)
#pragma unroll
                for (int mt = 0; mt < 2; mt++) {
                    mma_bf16(acc[mt][np * 2],     aH[mt], &bB[np][0]);
                    mma_bf16(acc[mt][np * 2 + 1], aH[mt], &bB[np][2]);
                }
        }
    }

#pragma unroll
    for (int mt = 0; mt < 2; mt++) {
        size_t m0 = mBase + wm * 32 + mt * 16 + (lane >> 2);
#pragma unroll
        for (int nt = 0; nt < 8; nt++) {
            int n = nBase + wn * 64 + nt * 8 + (lane & 3) * 2;
            float b0 = bias[n], b1 = bias[n + 1];
            float v0 = acc[mt][nt][0] + b0;
            float v1 = acc[mt][nt][1] + b1;
            float v2 = acc[mt][nt][2] + b0;
            float v3 = acc[mt][nt][3] + b1;
            if (relu) {
                v0 = fmaxf(v0, 0.f); v1 = fmaxf(v1, 0.f);
                v2 = fmaxf(v2, 0.f); v3 = fmaxf(v3, 0.f);
            }
            uint16_t h0, l0, h1, l1;
            f2hilo(v0, h0, l0); f2hilo(v1, h1, l1);
            *(uint32_t*)&Ohi[m0 * Nsz + n] = (uint32_t)h0 | ((uint32_t)h1 << 16);
            *(uint32_t*)&Olo[m0 * Nsz + n] = (uint32_t)l0 | ((uint32_t)l1 << 16);
            f2hilo(v2, h0, l0); f2hilo(v3, h1, l1);
            *(uint32_t*)&Ohi[(m0 + 8) * Nsz + n] = (uint32_t)h0 | ((uint32_t)h1 << 16);
            *(uint32_t*)&Olo[(m0 + 8) * Nsz + n] = (uint32_t)l0 | ((uint32_t)l1 << 16);
        }
    }
}

// ---------------- interaction via HMMA gram (bf16x3), 1 warp/sample ----------
// comb per sample: 32 rows x 128 k, bf16, 272B row stride (bank-walking),
// hi plane then lo plane. 8 samples/block, smem 8*17408 = 139264 B.
#define ISTRIDE 272
#define IPLANE  8704          // 32 * 272
#define ISAMP   17408         // 2 planes

__global__ __launch_bounds__(256, 1)
void interact_kernel(const uint16_t* __restrict__ Hhi, const uint16_t* __restrict__ Hlo,
                     const float* __restrict__ emb, const int* __restrict__ sidx,
                     uint16_t* __restrict__ Ohi, uint16_t* __restrict__ Olo) {
    extern __shared__ __align__(16) uint8_t ism[];
    const int warp = threadIdx.x >> 5;
    const int lane = threadIdx.x & 31;
    const size_t s = (size_t)blockIdx.x * 8 + warp;
    uint8_t* my = ism + warp * ISAMP;
    const uint32_t base = smem_u32(my);

    int idx26[26];
#pragma unroll
    for (int v = 0; v < 26; v++) idx26[v] = sidx[s * 26 + v] & (VOCAB - 1);

    // row 0 = h (already bf16 hi/lo pairs); also copy to output cols [0,128)
    {
        uint2 hh = *(const uint2*)&Hhi[s * 128 + lane * 4];
        uint2 ll = *(const uint2*)&Hlo[s * 128 + lane * 4];
        *(uint2*)(my + lane * 8) = hh;
        *(uint2*)(my + IPLANE + lane * 8) = ll;
        *(uint2*)&Ohi[s * 512 + lane * 4] = hh;
        *(uint2*)&Olo[s * 512 + lane * 4] = ll;
    }
    // zero pad rows 27..31 (both planes)
#pragma unroll
    for (int r = 27; r < 32; r++) {
        *(uint2*)(my + r * ISTRIDE + lane * 8) = make_uint2(0, 0);
        *(uint2*)(my + IPLANE + r * ISTRIDE + lane * 8) = make_uint2(0, 0);
    }

    // gather rows 1..26 in waves of 8 (MLP=8), split fp32 -> bf16 hi/lo
#pragma unroll
    for (int w0 = 0; w0 < 26; w0 += 8) {
        float4 e[8];
        const int cnt = (26 - w0 < 8) ? (26 - w0) : 8;
#pragma unroll
        for (int j = 0; j < 8; j++)
            if (j < cnt)
                e[j] = *(const float4*)&emb[(size_t)idx26[w0 + j] * 128 + lane * 4];
#pragma unroll
        for (int j = 0; j < 8; j++)
            if (j < cnt) {
                const int r = w0 + j + 1;
                float f[4] = {e[j].x, e[j].y, e[j].z, e[j].w};
                uint16_t h[4], l[4];
#pragma unroll
                for (int q = 0; q < 4; q++) f2hilo(f[q], h[q], l[q]);
                uint2 ph = make_uint2((uint32_t)h[0] | ((uint32_t)h[1] << 16),
                                      (uint32_t)h[2] | ((uint32_t)h[3] << 16));
                uint2 pl = make_uint2((uint32_t)l[0] | ((uint32_t)l[1] << 16),
                                      (uint32_t)l[2] | ((uint32_t)l[3] << 16));
                *(uint2*)(my + r * ISTRIDE + lane * 8) = ph;
                *(uint2*)(my + IPLANE + r * ISTRIDE + lane * 8) = pl;
            }
    }
    __syncwarp();

    // gram = comb @ comb^T via bf16x3 HMMA, 32x32 output
    float acc[2][4][4];
#pragma unroll
    for (int a = 0; a < 2; a++)
#pragma unroll
        for (int b = 0; b < 4; b++)
#pragma unroll
            for (int c = 0; c < 4; c++) acc[a][b][c] = 0.f;

    const uint32_t aoff = base + (uint32_t)(lane & 15) * ISTRIDE + (lane >> 4) * 16;
    const uint32_t boff = base + (uint32_t)((lane & 7) + ((lane >> 4) << 3)) * ISTRIDE
                        + (((lane >> 3) & 1) << 4);

#pragma unroll
    for (int ks = 0; ks < 8; ks++) {
        const uint32_t kb = ks * 32;
        uint32_t aH[2][4], aL[2][4], bB[2][4];
        ldsm4(aH[0], aoff + kb);
        ldsm4(aH[1], aoff + 16 * ISTRIDE + kb);
        ldsm4(aL[0], aoff + IPLANE + kb);
        ldsm4(aL[1], aoff + IPLANE + 16 * ISTRIDE + kb);
        ldsm4(bB[0], boff + kb);
        ldsm4(bB[1], boff + 16 * ISTRIDE + kb);

        // pass 1: aH x bH
#pragma unroll
        for (int g = 0; g < 2; g++)
#pragma unroll
            for (int mt = 0; mt < 2; mt++) {
                mma_bf16(acc[mt][g * 2],     aH[mt], &bB[g][0]);
                mma_bf16(acc[mt][g * 2 + 1], aH[mt], &bB[g][2]);
            }
        // pass 2: aL x bH, then reload bB with lo
#pragma unroll
        for (int g = 0; g < 2; g++) {
#pragma unroll
            for (int mt = 0; mt < 2; mt++) {
                mma_bf16(acc[mt][g * 2],     aL[mt], &bB[g][0]);
                mma_bf16(acc[mt][g * 2 + 1], aL[mt], &bB[g][2]);
            }
            ldsm4(bB[g], boff + IPLANE + g * 16 * ISTRIDE + kb);
        }
        // pass 3: aH x bL
#pragma unroll
        for (int g = 0; g < 2; g++)
#pragma unroll
            for (int mt = 0; mt < 2; mt++) {
                mma_bf16(acc[mt][g * 2],     aH[mt], &bB[g][0]);
                mma_bf16(acc[mt][g * 2 + 1], aH[mt], &bB[g][2]);
            }
    }

    // epilogue: store triu(27) entries -> cols [128, 506)
#pragma unroll
    for (int mt = 0; mt < 2; mt++)
#pragma unroll
        for (int nt = 0; nt < 4; nt++)
#pragma unroll
            for (int q = 0; q < 4; q++) {
                int i = mt * 16 + (lane >> 2) + ((q >> 1) << 3);
                int j = nt * 8 + (lane & 3) * 2 + (q & 1);
                if (i <= j && j < 27) {
                    int flat = 27 * i - (i * (i - 1)) / 2 + (j - i);
                    uint16_t h, l;
                    f2hilo(acc[mt][nt][q], h, l);
                    Ohi[s * 512 + 128 + flat] = h;
                    Olo[s * 512 + 128 + flat] = l;
                }
            }
    // zero pad cols [506, 512)
    if (lane < 6) {
        Ohi[s * 512 + 506 + lane] = 0;
        Olo[s * 512 + 506 + lane] = 0;
    }
}

// ---------------- final 256 -> 1 dot ----------------
__global__ void final_dot_kernel(const uint16_t* __restrict__ Ahi, const uint16_t* __restrict__ Alo,
                                 const float* __restrict__ w, const float* __restrict__ b,
                                 float* __restrict__ out) {
    const int warp = threadIdx.x >> 5;
    const int lane = threadIdx.x & 31;
    const size_t s = (size_t)blockIdx.x * 8 + warp;
    uint4 h4 = *(const uint4*)&Ahi[s * 256 + lane * 8];
    uint4 l4 = *(const uint4*)&Alo[s * 256 + lane * 8];
    uint32_t hw[4] = {h4.x, h4.y, h4.z, h4.w};
    uint32_t lw[4] = {l4.x, l4.y, l4.z, l4.w};
    float acc = 0.f;
#pragma unroll
    for (int q = 0; q < 4; q++) {
        float v0 = b2f((uint16_t)(hw[q] & 0xFFFF)) + b2f((uint16_t)(lw[q] & 0xFFFF));
        float v1 = b2f((uint16_t)(hw[q] >> 16))    + b2f((uint16_t)(lw[q] >> 16));
        acc += v0 * w[lane * 8 + q * 2];
        acc += v1 * w[lane * 8 + q * 2 + 1];
    }
#pragma unroll
    for (int o = 16; o; o >>= 1) acc += __shfl_xor_sync(0xFFFFFFFFu, acc, o);
    if (lane == 0) out[s] = acc + b[0];
}

// ---------------- host launch ----------------
extern "C" void kernel_launch(void* const* d_in, const int* in_sizes, int n_in,
                              void* d_out, int out_size) {
    const float* dense = (const float*)d_in[0];
    const int*   sidx  = (const int*)d_in[1];
    const float* emb   = (const float*)d_in[2];
    const float* bw0 = (const float*)d_in[3];  const float* bb0 = (const float*)d_in[4];
    const float* bw1 = (const float*)d_in[5];  const float* bb1 = (const float*)d_in[6];
    const float* bw2 = (const float*)d_in[7];  const float* bb2 = (const float*)d_in[8];
    const float* tw0 = (const float*)d_in[9];  const float* tb0 = (const float*)d_in[10];
    const float* tw1 = (const float*)d_in[11]; const float* tb1 = (const float*)d_in[12];
    const float* tw2 = (const float*)d_in[13]; const float* tb2 = (const float*)d_in[14];
    const float* tw3 = (const float*)d_in[15]; const float* tb3 = (const float*)d_in[16];
    const float* tw4 = (const float*)d_in[17]; const float* tb4 = (const float*)d_in[18];

    uint16_t *bufAh, *bufAl, *bufBh, *bufBl, *wth, *wtl;
    cudaGetSymbolAddress((void**)&bufAh, g_bufA_hi);
    cudaGetSymbolAddress((void**)&bufAl, g_bufA_lo);
    cudaGetSymbolAddress((void**)&bufBh, g_bufB_hi);
    cudaGetSymbolAddress((void**)&bufBl, g_bufB_lo);
    cudaGetSymbolAddress((void**)&wth, g_wt_hi);
    cudaGetSymbolAddress((void**)&wtl, g_wt_lo);

    const int DSM = 3 * STAGE_B;       // 98304
    const int ISM = 8 * ISAMP;         // 139264
    cudaFuncSetAttribute(gemm_hmma, cudaFuncAttributeMaxDynamicSharedMemorySize, DSM);
    cudaFuncSetAttribute(interact_kernel, cudaFuncAttributeMaxDynamicSharedMemorySize, ISM);

    dim3 blk(256);

    // conversions
    conv_dense_kernel<<<BATCH * 32 / 256, blk>>>(dense, bufAh, bufAl);
    conv_wt_t_kernel<<<dim3(512 / 32, 1),   blk>>>(bw0, wth + OFF_BW0, wtl + OFF_BW0, 13,   512,  32);
    conv_wt_t_kernel<<<dim3(256 / 32, 8),   blk>>>(bw1, wth + OFF_BW1, wtl + OFF_BW1, 512,  256,  512);
    conv_wt_t_kernel<<<dim3(128 / 32, 4),   blk>>>(bw2, wth + OFF_BW2, wtl + OFF_BW2, 256,  128,  256);
    conv_wt_t_kernel<<<dim3(1024 / 32, 8),  blk>>>(tw0, wth + OFF_TW0, wtl + OFF_TW0, 506,  1024, 512);
    conv_wt_t_kernel<<<dim3(1024 / 32, 16), blk>>>(tw1, wth + OFF_TW1, wtl + OFF_TW1, 1024, 1024, 1024);
    conv_wt_t_kernel<<<dim3(512 / 32, 16),  blk>>>(tw2, wth + OFF_TW2, wtl + OFF_TW2, 1024, 512,  1024);
    conv_wt_t_kernel<<<dim3(256 / 32, 8),   blk>>>(tw3, wth + OFF_TW3, wtl + OFF_TW3, 512,  256,  512);

    // bottom MLP
    gemm_hmma<<<dim3(4, 512), blk, DSM>>>(bufAh, bufAl, wth + OFF_BW0, wtl + OFF_BW0, bb0, bufBh, bufBl, 512, 32, 1);
    gemm_hmma<<<dim3(2, 512), blk, DSM>>>(bufBh, bufBl, wth + OFF_BW1, wtl + OFF_BW1, bb1, bufAh, bufAl, 256, 512, 1);
    gemm_hmma<<<dim3(1, 512), blk, DSM>>>(bufAh, bufAl, wth + OFF_BW2, wtl + OFF_BW2, bb2, bufBh, bufBl, 128, 256, 1);

    // gather + interaction (HMMA gram) -> [B, 512]
    interact_kernel<<<BATCH / 8, blk, ISM>>>(bufBh, bufBl, emb, sidx, bufAh, bufAl);

    // top MLP
    gemm_hmma<<<dim3(8, 512), blk, DSM>>>(bufAh, bufAl, wth + OFF_TW0, wtl + OFF_TW0, tb0, bufBh, bufBl, 1024, 512, 1);
    gemm_hmma<<<dim3(8, 512), blk, DSM>>>(bufBh, bufBl, wth + OFF_TW1, wtl + OFF_TW1, tb1, bufAh, bufAl, 1024, 1024, 1);
    gemm_hmma<<<dim3(4, 512), blk, DSM>>>(bufAh, bufAl, wth + OFF_TW2, wtl + OFF_TW2, tb2, bufBh, bufBl, 512, 1024, 1);
    gemm_hmma<<<dim3(2, 512), blk, DSM>>>(bufBh, bufBl, wth + OFF_TW3, wtl + OFF_TW3, tb3, bufAh, bufAl, 256, 512, 1);

    // final 256 -> 1
    final_dot_kernel<<<BATCH / 8, blk>>>(bufAh, bufAl, tw4, tb4, (float*)d_out);
}